// round 14
// baseline (speedup 1.0000x reference)
#include <cuda_runtime.h>
#include <cstdint>

// PatchTransformer R14: attack the LSU-issue floor. 4096 blocks (proven
// balance granularity) x 64 threads (8x8), 4 px/thread via float4 clean/out
// (6M -> 1.5M LSU ops on the copy path), launch_bounds(64,28) -> ~4144
// concurrent CTAs -> single wave WITH fine-grained balance. Warp-level ballot
// candidate mask (no smem barrier). Exact-fp replication of the reference
// grid_sample chain (rn intrinsics block FMA contraction): reference gates on
// mask==1.0 and adv==0.0 equality.

#define S 1024
#define PS 256
#define NP 8

__global__ __launch_bounds__(64, 28)
void patch_transformer_kernel(const float* __restrict__ patches,   // [8,3,256,256]
                              const float* __restrict__ locs,      // [8,2]
                              const float* __restrict__ clean,     // [3,1024,1024]
                              float* __restrict__ out)             // [3,1024,1024]
{
    const int tid  = threadIdx.y * 8 + threadIdx.x;   // 0..63
    const int lane = tid & 31;

    const int bw0 = blockIdx.x * 32;
    const int bh0 = blockIdx.y * 8;

    const int w0 = bw0 + threadIdx.x * 4;   // 4 px along w
    const int h  = bh0 + threadIdx.y;
    const int pix = h * S + w0;

    // Issue vectorized clean loads first (3x LDG.128 = 48B/thread in flight);
    // mask computation overlaps their latency.
    float4 a0 = *(const float4*)(clean + pix);
    float4 a1 = *(const float4*)(clean + pix + S * S);
    float4 a2 = *(const float4*)(clean + pix + 2 * S * S);

    // Per-lane patch location preload (lanes 0..7 own one patch each).
    float plx = 0.0f, ply = 0.0f;
    if (lane < NP) {
        plx = __ldg(locs + 2 * lane + 0);
        ply = __ldg(locs + 2 * lane + 1);
    }

    // Warp-level candidate mask over this warp's 32x4 strip.
    // Conservative: exact sample coord x == w - 512*lx to within <1e-3 px;
    // a pixel can touch patch data only if x in [-1,257). +-2 px margin.
    const int hy0 = bh0 + 4 * (tid >> 5);   // warp covers rows hy0..hy0+3
    bool hit = false;
    if (lane < NP) {
        const float px = 512.0f * plx;
        const float py = 512.0f * ply;
        hit = ((float)bw0        <= px + 258.0f) &&
              ((float)(bw0 + 31) >= px - 2.0f)   &&
              ((float)hy0        <= py + 258.0f) &&
              ((float)(hy0 + 3)  >= py - 2.0f);
    }
    unsigned cmask = __ballot_sync(0xFFFFFFFFu, hit) & 0xFFu;   // warp-uniform

    if (cmask) {
        float v[3][4] = {{a0.x, a0.y, a0.z, a0.w},
                         {a1.x, a1.y, a1.z, a1.w},
                         {a2.x, a2.y, a2.z, a2.w}};

        // Normalized grid y coord, exact reference chain (exact fp32 steps).
        const float gy = __fadd_rn(__fmul_rn(__fmul_rn(__fadd_rn((float)h, 0.5f), 2.0f),
                                             (1.0f / 1024.0f)), -1.0f);

        do {
            const int n = __ffs(cmask) - 1;   // ascending = reference paste order
            cmask &= cmask - 1;

            const float lx = __shfl_sync(0xFFFFFFFFu, plx, n);
            const float ly = __shfl_sync(0xFFFFFFFFu, ply, n);

            // y chain shared by the thread's 4 pixels (same h).
            const float gry = __fadd_rn(gy, -ly);
            const float y = __fmul_rn(__fadd_rn(__fmul_rn(__fadd_rn(gry, 1.0f), 1024.0f), -1.0f), 0.5f);
            const float y0f = floorf(y);
            const int iy0 = (int)y0f;
            if ((unsigned)(iy0 + 1) > 256u) continue;

            const float wy1 = __fadd_rn(y, -y0f);
            const float wy0 = __fadd_rn(1.0f, -wy1);
            const bool vy0 = (iy0 >= 0);
            const bool cy1 = (iy0 <= PS - 2);

            const float* P = patches + (size_t)n * 3 * PS * PS;
            const int rowoff = iy0 * PS;

            #pragma unroll
            for (int k = 0; k < 4; ++k) {
                // Normalized grid x coord for pixel w0+k (exact fp32 steps).
                const float gx = __fadd_rn(__fmul_rn(__fmul_rn(__fadd_rn((float)(w0 + k), 0.5f), 2.0f),
                                                     (1.0f / 1024.0f)), -1.0f);
                const float grx = __fadd_rn(gx, -lx);
                const float x = __fmul_rn(__fadd_rn(__fmul_rn(__fadd_rn(grx, 1.0f), 1024.0f), -1.0f), 0.5f);
                const float x0f = floorf(x);
                const int ix0 = (int)x0f;
                if ((unsigned)(ix0 + 1) > 256u) continue;

                const float wx1 = __fadd_rn(x, -x0f);
                const float wx0 = __fadd_rn(1.0f, -wx1);

                const float w00 = __fmul_rn(wy0, wx0);
                const float w01 = __fmul_rn(wy0, wx1);
                const float w10 = __fmul_rn(wy1, wx0);
                const float w11 = __fmul_rn(wy1, wx1);

                const bool vx0 = (ix0 >= 0);
                // mask_w = left-associated sum of valid*weight, exactly as
                // reference (+1 taps always frame-valid inside footprint).
                const float msum = __fadd_rn(__fadd_rn(__fadd_rn(
                                       (vy0 && vx0) ? w00 : 0.0f,
                                       vy0 ? w01 : 0.0f),
                                       vx0 ? w10 : 0.0f),
                                       w11);
                if (msum != 1.0f) continue;

                const bool cx1 = (ix0 <= PS - 2);
                const bool t00v = vy0 && vx0;
                const bool t01v = vy0 && cx1;
                const bool t10v = cy1 && vx0;
                const bool t11v = cy1 && cx1;
                if (!(t00v | t01v | t10v | t11v)) continue;

                const int o00 = rowoff + ix0;
                #pragma unroll
                for (int c = 0; c < 3; ++c) {
                    const float* B = P + c * PS * PS;
                    const float t00 = t00v ? __fmul_rn(__ldg(B + o00),          w00) : 0.0f;
                    const float t01 = t01v ? __fmul_rn(__ldg(B + o00 + 1),      w01) : 0.0f;
                    const float t10 = t10v ? __fmul_rn(__ldg(B + o00 + PS),     w10) : 0.0f;
                    const float t11 = t11v ? __fmul_rn(__ldg(B + o00 + PS + 1), w11) : 0.0f;
                    const float p = __fadd_rn(__fadd_rn(__fadd_rn(t00, t01), t10), t11);
                    if (p != 0.0f) v[c][k] = p;
                }
            }
        } while (cmask);

        a0 = make_float4(v[0][0], v[0][1], v[0][2], v[0][3]);
        a1 = make_float4(v[1][0], v[1][1], v[1][2], v[1][3]);
        a2 = make_float4(v[2][0], v[2][1], v[2][2], v[2][3]);
    }

    *(float4*)(out + pix)             = a0;
    *(float4*)(out + pix + S * S)     = a1;
    *(float4*)(out + pix + 2 * S * S) = a2;
}

extern "C" void kernel_launch(void* const* d_in, const int* in_sizes, int n_in,
                              void* d_out, int out_size) {
    const float* patches = (const float*)d_in[0];   // (8,3,256,256)
    const float* locs    = (const float*)d_in[1];   // (8,2)
    const float* clean   = (const float*)d_in[2];   // (3,1024,1024)
    float* out = (float*)d_out;                     // (1,3,1024,1024)

    dim3 block(8, 8);                   // 64 threads, 4 px/thread (float4)
    dim3 grid(S / 32, S / 8);           // 32 x 128 = 4096 blocks (32x8 tiles)
    patch_transformer_kernel<<<grid, block>>>(patches, locs, clean, out);
}

// round 15
// speedup vs baseline: 1.4651x; 1.4651x over previous
#include <cuda_runtime.h>
#include <cstdint>

// PatchTransformer R15: two 32x8 tiles per block (bid and bid+2048 -> same
// column strip, rows 512 apart, so at most ONE tile of the pair is
// patch-covered: balanced by construction at 4096-tile granularity, 2.3
// waves for rebalancing). All 6 clean loads issued upfront (2x bytes and 2x
// issue-work in flight per warp generation vs R8). Warp-level row ballot
// masks, no smem, no syncthreads. Exact-fp replication of the reference
// grid_sample chain (rn intrinsics block FMA contraction): reference gates on
// mask==1.0 and adv==0.0 equality.

#define S 1024
#define PS 256
#define NP 8

__global__ __launch_bounds__(256, 6)
void patch_transformer_kernel(const float* __restrict__ patches,   // [8,3,256,256]
                              const float* __restrict__ locs,      // [8,2]
                              const float* __restrict__ clean,     // [3,1024,1024]
                              float* __restrict__ out)             // [3,1024,1024]
{
    const int lane = threadIdx.x;          // 0..31
    const int row  = threadIdx.y;          // 0..7

    const int bid = blockIdx.x;            // 0..2047
    const int bw0 = (bid & 31) * 32;       // column strip (same for both tiles)
    const int h0  = (bid >> 5) * 8 + row;  // tile0 row: 0..511
    const int h1  = h0 + 512;              // tile1 row: 512..1023

    const int w    = bw0 + lane;
    const int pix0 = h0 * S + w;
    const int pix1 = h1 * S + w;

    // ---- Issue ALL 6 clean loads upfront (24B/thread in flight).
    float c00 = clean[pix0];
    float c01 = clean[pix0 + S * S];
    float c02 = clean[pix0 + 2 * S * S];
    float c10 = clean[pix1];
    float c11 = clean[pix1 + S * S];
    float c12 = clean[pix1 + 2 * S * S];

    // Per-lane patch location preload (lanes 0..7 own one patch each).
    float plx = 0.0f, ply = 0.0f;
    if (lane < NP) {
        plx = __ldg(locs + 2 * lane + 0);
        ply = __ldg(locs + 2 * lane + 1);
    }
    const float ppx = 512.0f * plx;
    const float ppy = 512.0f * ply;

    // Conservative candidate tests (warp = one 32px row).
    // Exact sample coord x == w - 512*lx to within <1e-3 px; pixel can touch
    // patch data only if x in [-1,257). +-2 px margin: strictly conservative.
    const bool xhit = (lane < NP) &&
                      ((float)bw0        <= ppx + 258.0f) &&
                      ((float)(bw0 + 31) >= ppx - 2.0f);
    const bool hit0 = xhit && ((float)h0 <= ppy + 258.0f) && ((float)h0 >= ppy - 2.0f);
    const bool hit1 = xhit && ((float)h1 <= ppy + 258.0f) && ((float)h1 >= ppy - 2.0f);
    unsigned cmask0 = __ballot_sync(0xFFFFFFFFu, hit0) & 0xFFu;
    unsigned cmask1 = __ballot_sync(0xFFFFFFFFu, hit1) & 0xFFu;

    // Normalized grid x coord (same w for both tiles), exact reference chain.
    const float gx = __fadd_rn(__fmul_rn(__fmul_rn(__fadd_rn((float)w, 0.5f), 2.0f),
                                         (1.0f / 1024.0f)), -1.0f);

    // ================= tile 0 =================
    if (cmask0) {
        const float gy = __fadd_rn(__fmul_rn(__fmul_rn(__fadd_rn((float)h0, 0.5f), 2.0f),
                                             (1.0f / 1024.0f)), -1.0f);
        do {
            const int n = __ffs(cmask0) - 1;   // ascending = reference paste order
            cmask0 &= cmask0 - 1;

            const float lx = __shfl_sync(0xFFFFFFFFu, plx, n);
            const float ly = __shfl_sync(0xFFFFFFFFu, ply, n);

            const float gry = __fadd_rn(gy, -ly);
            const float y = __fmul_rn(__fadd_rn(__fmul_rn(__fadd_rn(gry, 1.0f), 1024.0f), -1.0f), 0.5f);
            const float y0f = floorf(y);
            const int iy0 = (int)y0f;
            if ((unsigned)(iy0 + 1) > 256u) continue;

            const float grx = __fadd_rn(gx, -lx);
            const float x = __fmul_rn(__fadd_rn(__fmul_rn(__fadd_rn(grx, 1.0f), 1024.0f), -1.0f), 0.5f);
            const float x0f = floorf(x);
            const int ix0 = (int)x0f;
            if ((unsigned)(ix0 + 1) > 256u) continue;

            const float wx1 = __fadd_rn(x, -x0f);
            const float wx0 = __fadd_rn(1.0f, -wx1);
            const float wy1 = __fadd_rn(y, -y0f);
            const float wy0 = __fadd_rn(1.0f, -wy1);

            const float w00 = __fmul_rn(wy0, wx0);
            const float w01 = __fmul_rn(wy0, wx1);
            const float w10 = __fmul_rn(wy1, wx0);
            const float w11 = __fmul_rn(wy1, wx1);

            const bool vx0 = (ix0 >= 0);
            const bool vy0 = (iy0 >= 0);
            // mask_w = left-associated sum of valid*weight, exactly as
            // reference (+1 taps always frame-valid inside footprint).
            const float msum = __fadd_rn(__fadd_rn(__fadd_rn(
                                   (vy0 && vx0) ? w00 : 0.0f,
                                   vy0 ? w01 : 0.0f),
                                   vx0 ? w10 : 0.0f),
                                   w11);
            if (msum != 1.0f) continue;

            const bool cx1 = (ix0 <= PS - 2);
            const bool cy1 = (iy0 <= PS - 2);
            const bool t00v = vy0 && vx0;
            const bool t01v = vy0 && cx1;
            const bool t10v = cy1 && vx0;
            const bool t11v = cy1 && cx1;
            if (!(t00v | t01v | t10v | t11v)) continue;

            const float* P = patches + (size_t)n * 3 * PS * PS;
            const int o00 = iy0 * PS + ix0;

            #pragma unroll
            for (int c = 0; c < 3; ++c) {
                const float* B = P + c * PS * PS;
                const float t00 = t00v ? __fmul_rn(__ldg(B + o00),          w00) : 0.0f;
                const float t01 = t01v ? __fmul_rn(__ldg(B + o00 + 1),      w01) : 0.0f;
                const float t10 = t10v ? __fmul_rn(__ldg(B + o00 + PS),     w10) : 0.0f;
                const float t11 = t11v ? __fmul_rn(__ldg(B + o00 + PS + 1), w11) : 0.0f;
                const float p = __fadd_rn(__fadd_rn(__fadd_rn(t00, t01), t10), t11);
                if (p != 0.0f) {
                    if (c == 0) c00 = p;
                    else if (c == 1) c01 = p;
                    else c02 = p;
                }
            }
        } while (cmask0);
    }

    out[pix0]             = c00;
    out[pix0 + S * S]     = c01;
    out[pix0 + 2 * S * S] = c02;

    // ================= tile 1 =================
    if (cmask1) {
        const float gy = __fadd_rn(__fmul_rn(__fmul_rn(__fadd_rn((float)h1, 0.5f), 2.0f),
                                             (1.0f / 1024.0f)), -1.0f);
        do {
            const int n = __ffs(cmask1) - 1;
            cmask1 &= cmask1 - 1;

            const float lx = __shfl_sync(0xFFFFFFFFu, plx, n);
            const float ly = __shfl_sync(0xFFFFFFFFu, ply, n);

            const float gry = __fadd_rn(gy, -ly);
            const float y = __fmul_rn(__fadd_rn(__fmul_rn(__fadd_rn(gry, 1.0f), 1024.0f), -1.0f), 0.5f);
            const float y0f = floorf(y);
            const int iy0 = (int)y0f;
            if ((unsigned)(iy0 + 1) > 256u) continue;

            const float grx = __fadd_rn(gx, -lx);
            const float x = __fmul_rn(__fadd_rn(__fmul_rn(__fadd_rn(grx, 1.0f), 1024.0f), -1.0f), 0.5f);
            const float x0f = floorf(x);
            const int ix0 = (int)x0f;
            if ((unsigned)(ix0 + 1) > 256u) continue;

            const float wx1 = __fadd_rn(x, -x0f);
            const float wx0 = __fadd_rn(1.0f, -wx1);
            const float wy1 = __fadd_rn(y, -y0f);
            const float wy0 = __fadd_rn(1.0f, -wy1);

            const float w00 = __fmul_rn(wy0, wx0);
            const float w01 = __fmul_rn(wy0, wx1);
            const float w10 = __fmul_rn(wy1, wx0);
            const float w11 = __fmul_rn(wy1, wx1);

            const bool vx0 = (ix0 >= 0);
            const bool vy0 = (iy0 >= 0);
            const float msum = __fadd_rn(__fadd_rn(__fadd_rn(
                                   (vy0 && vx0) ? w00 : 0.0f,
                                   vy0 ? w01 : 0.0f),
                                   vx0 ? w10 : 0.0f),
                                   w11);
            if (msum != 1.0f) continue;

            const bool cx1 = (ix0 <= PS - 2);
            const bool cy1 = (iy0 <= PS - 2);
            const bool t00v = vy0 && vx0;
            const bool t01v = vy0 && cx1;
            const bool t10v = cy1 && vx0;
            const bool t11v = cy1 && cx1;
            if (!(t00v | t01v | t10v | t11v)) continue;

            const float* P = patches + (size_t)n * 3 * PS * PS;
            const int o00 = iy0 * PS + ix0;

            #pragma unroll
            for (int c = 0; c < 3; ++c) {
                const float* B = P + c * PS * PS;
                const float t00 = t00v ? __fmul_rn(__ldg(B + o00),          w00) : 0.0f;
                const float t01 = t01v ? __fmul_rn(__ldg(B + o00 + 1),      w01) : 0.0f;
                const float t10 = t10v ? __fmul_rn(__ldg(B + o00 + PS),     w10) : 0.0f;
                const float t11 = t11v ? __fmul_rn(__ldg(B + o00 + PS + 1), w11) : 0.0f;
                const float p = __fadd_rn(__fadd_rn(__fadd_rn(t00, t01), t10), t11);
                if (p != 0.0f) {
                    if (c == 0) c10 = p;
                    else if (c == 1) c11 = p;
                    else c12 = p;
                }
            }
        } while (cmask1);
    }

    out[pix1]             = c10;
    out[pix1 + S * S]     = c11;
    out[pix1 + 2 * S * S] = c12;
}

extern "C" void kernel_launch(void* const* d_in, const int* in_sizes, int n_in,
                              void* d_out, int out_size) {
    const float* patches = (const float*)d_in[0];   // (8,3,256,256)
    const float* locs    = (const float*)d_in[1];   // (8,2)
    const float* clean   = (const float*)d_in[2];   // (3,1024,1024)
    float* out = (float*)d_out;                     // (1,3,1024,1024)

    dim3 block(32, 8);
    patch_transformer_kernel<<<2048, block>>>(patches, locs, clean, out);
}

// round 16
// speedup vs baseline: 1.5045x; 1.0269x over previous
#include <cuda_runtime.h>
#include <cstdint>

// PatchTransformer R16: R8's exact proven configuration (4096 x 32x8 tiles,
// 256 threads, block-uniform ballot mask, multi-wave rebalancing) with ONE
// change: copy-only blocks (cmask==0, ~55%) run a 192-thread float4 copy
// (4x fewer LSU ops, ~6x fewer instructions) instead of the scalar path.
// Patch blocks are bit-identical to R8. Exact-fp replication of the reference
// grid_sample chain (rn intrinsics block FMA contraction): reference gates on
// mask==1.0 and adv==0.0 equality.

#define S 1024
#define PS 256
#define NP 8

__global__ __launch_bounds__(256, 8)
void patch_transformer_kernel(const float* __restrict__ patches,   // [8,3,256,256]
                              const float* __restrict__ locs,      // [8,2]
                              const float* __restrict__ clean,     // [3,1024,1024]
                              float* __restrict__ out)             // [3,1024,1024]
{
    __shared__ float s_loc[2 * NP];
    __shared__ unsigned s_cmask;

    const int tid = threadIdx.y * 32 + threadIdx.x;
    if (tid < 2 * NP) s_loc[tid] = locs[tid];

    const int bw0 = blockIdx.x * 32;
    const int bh0 = blockIdx.y * 8;

    // Warp 0: block-uniform candidate mask. Conservative: exact sample coord
    // x == w - 512*lx to within <1e-3 px; a pixel can touch patch data only
    // if x in [-1,257). +-2 px margin keeps it strictly conservative.
    if (tid < 32) {
        bool hit = false;
        if (tid < NP) {
            const float px = 512.0f * __ldg(locs + 2 * tid + 0);
            const float py = 512.0f * __ldg(locs + 2 * tid + 1);
            hit = ((float)bw0        <= px + 258.0f) &&
                  ((float)(bw0 + 31) >= px - 2.0f)   &&
                  ((float)bh0        <= py + 258.0f) &&
                  ((float)(bh0 + 7)  >= py - 2.0f);
        }
        const unsigned bal = __ballot_sync(0xFFFFFFFFu, hit);
        if (tid == 0) s_cmask = bal & 0xFFu;
    }
    __syncthreads();

    unsigned cmask = s_cmask;

    if (cmask == 0) {
        // ---- Pure-copy tile: 192 threads move the whole 32x8x3 tile as
        // float4 (1 LDG.128 + 1 STG.128 per thread). Identical bits out.
        if (tid < 192) {
            const int c   = tid >> 6;            // channel 0..2
            const int e   = (tid & 63) << 2;     // element 0,4,...,252 in tile
            const int row = e >> 5;              // 0..7
            const int col = e & 31;              // 0,4,8,...,28
            const int off = c * S * S + (bh0 + row) * S + bw0 + col;
            const float4 v = *(const float4*)(clean + off);
            *(float4*)(out + off) = v;
        }
        return;
    }

    // ---- Patch tile: R8's scalar per-pixel path, bit-identical.
    const int w = bw0 + threadIdx.x;
    const int h = bh0 + threadIdx.y;
    const int pix = h * S + w;

    float v0 = clean[pix];
    float v1 = clean[pix + S * S];
    float v2 = clean[pix + 2 * S * S];

    // Normalized grid coords, exact reference chain (all steps exact fp32).
    const float gx = __fadd_rn(__fmul_rn(__fmul_rn(__fadd_rn((float)w, 0.5f), 2.0f),
                                         (1.0f / 1024.0f)), -1.0f);
    const float gy = __fadd_rn(__fmul_rn(__fmul_rn(__fadd_rn((float)h, 0.5f), 2.0f),
                                         (1.0f / 1024.0f)), -1.0f);

    do {
        const int n = __ffs(cmask) - 1;   // ascending = reference paste order
        cmask &= cmask - 1;

        const float lx = s_loc[2 * n + 0];
        const float ly = s_loc[2 * n + 1];

        // Exact reference chain (bit-for-bit).
        const float gry = __fadd_rn(gy, -ly);
        const float y = __fmul_rn(__fadd_rn(__fmul_rn(__fadd_rn(gry, 1.0f), 1024.0f), -1.0f), 0.5f);
        const float y0f = floorf(y);
        const int iy0 = (int)y0f;
        if ((unsigned)(iy0 + 1) > 256u) continue;

        const float grx = __fadd_rn(gx, -lx);
        const float x = __fmul_rn(__fadd_rn(__fmul_rn(__fadd_rn(grx, 1.0f), 1024.0f), -1.0f), 0.5f);
        const float x0f = floorf(x);
        const int ix0 = (int)x0f;
        if ((unsigned)(ix0 + 1) > 256u) continue;

        const float wx1 = __fadd_rn(x, -x0f);
        const float wx0 = __fadd_rn(1.0f, -wx1);
        const float wy1 = __fadd_rn(y, -y0f);
        const float wy0 = __fadd_rn(1.0f, -wy1);

        const float w00 = __fmul_rn(wy0, wx0);
        const float w01 = __fmul_rn(wy0, wx1);
        const float w10 = __fmul_rn(wy1, wx0);
        const float w11 = __fmul_rn(wy1, wx1);

        const bool vx0 = (ix0 >= 0);
        const bool vy0 = (iy0 >= 0);
        // mask_w = left-associated sum of valid*weight, exactly as reference
        // (inside the footprint the +1 taps are always frame-valid).
        const float msum = __fadd_rn(__fadd_rn(__fadd_rn(
                               (vy0 && vx0) ? w00 : 0.0f,
                               vy0 ? w01 : 0.0f),
                               vx0 ? w10 : 0.0f),
                               w11);
        if (msum != 1.0f) continue;

        const bool cx1 = (ix0 <= PS - 2);
        const bool cy1 = (iy0 <= PS - 2);
        const bool t00v = vy0 && vx0;
        const bool t01v = vy0 && cx1;
        const bool t10v = cy1 && vx0;
        const bool t11v = cy1 && cx1;
        if (!(t00v | t01v | t10v | t11v)) continue;

        const float* P = patches + (size_t)n * 3 * PS * PS;
        const int o00 = iy0 * PS + ix0;

        #pragma unroll
        for (int c = 0; c < 3; ++c) {
            const float* B = P + c * PS * PS;
            const float t00 = t00v ? __fmul_rn(__ldg(B + o00),          w00) : 0.0f;
            const float t01 = t01v ? __fmul_rn(__ldg(B + o00 + 1),      w01) : 0.0f;
            const float t10 = t10v ? __fmul_rn(__ldg(B + o00 + PS),     w10) : 0.0f;
            const float t11 = t11v ? __fmul_rn(__ldg(B + o00 + PS + 1), w11) : 0.0f;
            const float p = __fadd_rn(__fadd_rn(__fadd_rn(t00, t01), t10), t11);
            if (p != 0.0f) {
                if (c == 0) v0 = p;
                else if (c == 1) v1 = p;
                else v2 = p;
            }
        }
    } while (cmask);

    out[pix]             = v0;
    out[pix + S * S]     = v1;
    out[pix + 2 * S * S] = v2;
}

extern "C" void kernel_launch(void* const* d_in, const int* in_sizes, int n_in,
                              void* d_out, int out_size) {
    const float* patches = (const float*)d_in[0];   // (8,3,256,256)
    const float* locs    = (const float*)d_in[1];   // (8,2)
    const float* clean   = (const float*)d_in[2];   // (3,1024,1024)
    float* out = (float*)d_out;                     // (1,3,1024,1024)

    dim3 block(32, 8);
    dim3 grid(S / 32, S / 8);   // 32 x 128 = 4096 blocks (32x8 tiles)
    patch_transformer_kernel<<<grid, block>>>(patches, locs, clean, out);
}